// round 9
// baseline (speedup 1.0000x reference)
#include <cuda_runtime.h>
#include <cstdint>

// Problem constants (from reference setup_inputs)
#define PB 16
#define PL 4096
#define PD 768
#define PS 128
#define D4 (PD / 4)          // 192 float4 per row
#define THREADS D4           // one float4 column per thread
#define NWARPS (THREADS / 32)

__device__ __forceinline__ void acc4(const float4 (&v)[4], float4& a,
                                     int& cx, int& cy, int& cz, int& cw) {
#pragma unroll
    for (int k = 0; k < 4; k++) {
        a.x += v[k].x; a.y += v[k].y; a.z += v[k].z; a.w += v[k].w;
        cx += (v[k].x != 0.f);
        cy += (v[k].y != 0.f);
        cz += (v[k].z != 0.f);
        cw += (v[k].w != 0.f);
    }
}

__device__ __forceinline__ void ld4(float4 (&v)[4], const float4* __restrict__ p) {
    v[0] = __ldg(p + 0 * D4);
    v[1] = __ldg(p + 1 * D4);
    v[2] = __ldg(p + 2 * D4);
    v[3] = __ldg(p + 3 * D4);
}

// One CTA per (b, segment-pair): grid = 1024 = exactly one wave at occ>=7,
// halving per-segment prologue cost and removing the wave transition.
// Inside: explicit 2-stage rotating register pipeline per segment (loads for
// the next 4-token batch issued before the previous batch is accumulated),
// both gather rows issued in the prologue, evict-first output stores.
__global__ __launch_bounds__(THREADS) void pooling_kernel(
    const float* __restrict__ wv,            // [B, L, D]
    const int* __restrict__ rep_ids,         // [B, S]
    const int* __restrict__ rep_mask,        // [B, S] bool as int32
    const int* __restrict__ lengths,         // [B, S]
    const int* __restrict__ len_mask,        // [B, S] bool as int32
    float* __restrict__ out,                 // [B, 2S, D] (+ mask tail)
    int write_mask)
{
    const int blk = blockIdx.x;
    const int b = blk >> 6;              // / (PS/2)
    const int s0 = (blk & 63) << 1;      // first of the two segments
    const int tid = threadIdx.x;
    const int lane = tid & 31;
    const int wid = tid >> 5;

    __shared__ int sred[NWARPS];

    // ---- start0 = sum_{j < s0} lengths[b, j] (block reduction) ----
    const int* lrow = lengths + b * PS;
    int part = (tid < s0) ? __ldg(&lrow[tid]) : 0;   // tid<192, s0<=126
#pragma unroll
    for (int o = 16; o > 0; o >>= 1)
        part += __shfl_down_sync(0xffffffffu, part, o);
    if (lane == 0) sred[wid] = part;
    __syncthreads();
    int start = 0;
#pragma unroll
    for (int w = 0; w < NWARPS; w++) start += sred[w];

    const float4* __restrict__ wvb =
        reinterpret_cast<const float4*>(wv) + (unsigned)b * (PL * D4);
    float4* __restrict__ outb =
        reinterpret_cast<float4*>(out) + (unsigned)b * (2 * PS * D4);

    // ---- prologue: both gather rows + scalars issued early ----
    const int bs0 = b * PS + s0;
    int id0 = __ldg(&rep_ids[bs0]);
    int id1 = __ldg(&rep_ids[bs0 + 1]);
    if (id0 < 0) id0 = 0; if (id0 >= PL) id0 = PL - 1;
    if (id1 < 0) id1 = 0; if (id1 >= PL) id1 = PL - 1;
    float4 g0 = __ldg(&wvb[(unsigned)id0 * D4 + tid]);
    float4 g1 = __ldg(&wvb[(unsigned)id1 * D4 + tid]);
    const float mrep0 = rep_mask[bs0] ? 1.f : 0.f;
    const float mrep1 = rep_mask[bs0 + 1] ? 1.f : 0.f;
    const float mlen0 = len_mask[bs0] ? 1.f : 0.f;
    const float mlen1 = len_mask[bs0 + 1] ? 1.f : 0.f;
    const int len0 = __ldg(&lrow[s0]);
    const int len1 = __ldg(&lrow[s0 + 1]);

#pragma unroll
    for (int seg = 0; seg < 2; seg++) {
        const int s = s0 + seg;
        const int bs = bs0 + seg;
        const int len = seg ? len1 : len0;

        int st = start;
        int end = st + len;
        if (st > PL) st = PL;
        if (end > PL) end = PL;
        start += len;

        const float4* __restrict__ p = wvb + (unsigned)st * D4 + tid;

        float4 acc = make_float4(0.f, 0.f, 0.f, 0.f);
        int cx = 0, cy = 0, cz = 0, cw = 0;

        const int n = end - st;
        float4 va[4], vb4[4];
        const int nb = n >> 2;
        if (nb > 0) {
            ld4(va, p); p += 4 * D4;
            int i = 1;
            for (; i + 1 < nb; i += 2) {
                ld4(vb4, p); p += 4 * D4;
                acc4(va, acc, cx, cy, cz, cw);
                ld4(va, p); p += 4 * D4;
                acc4(vb4, acc, cx, cy, cz, cw);
            }
            if (i < nb) {
                ld4(vb4, p); p += 4 * D4;
                acc4(va, acc, cx, cy, cz, cw);
                acc4(vb4, acc, cx, cy, cz, cw);
            } else {
                acc4(va, acc, cx, cy, cz, cw);
            }
        }
        for (int r = n & 3; r > 0; r--) {
            float4 v = __ldg(p); p += D4;
            acc.x += v.x; acc.y += v.y; acc.z += v.z; acc.w += v.w;
            cx += (v.x != 0.f); cy += (v.y != 0.f);
            cz += (v.z != 0.f); cw += (v.w != 0.f);
        }

        // ---- block-reduce total nonzero count ----
        int nz = cx + cy + cz + cw;
#pragma unroll
        for (int o = 16; o > 0; o >>= 1)
            nz += __shfl_down_sync(0xffffffffu, nz, o);
        __syncthreads();            // protect sred reuse
        if (lane == 0) sred[wid] = nz;
        __syncthreads();
        int total_nz = 0;
#pragma unroll
        for (int w = 0; w < NWARPS; w++) total_nz += sred[w];

        const float mlen = seg ? mlen1 : mlen0;
        const float mrep = seg ? mrep1 : mrep0;

        float4 mv;
        if (total_nz == 0) {
            mv = __ldg(&reinterpret_cast<const float4*>(wv)[tid]);  // wv[0,0,:]
        } else {
            mv.x = acc.x / (float)(cx ? cx : 1);
            mv.y = acc.y / (float)(cy ? cy : 1);
            mv.z = acc.z / (float)(cz ? cz : 1);
            mv.w = acc.w / (float)(cw ? cw : 1);
        }
        mv.x *= mlen; mv.y *= mlen; mv.z *= mlen; mv.w *= mlen;
        __stcs(&outb[(unsigned)(PS + s) * D4 + tid], mv);           // mean row

        float4 g = seg ? g1 : g0;
        g.x *= mrep; g.y *= mrep; g.z *= mrep; g.w *= mrep;
        __stcs(&outb[(unsigned)s * D4 + tid], g);                   // rep row

        if (write_mask && tid == 0) {
            float* mo = out + (size_t)PB * 2 * PS * PD;
            mo[b * 2 * PS + s] = mrep;
            mo[b * 2 * PS + PS + s] = mlen;
        }
    }
}

extern "C" void kernel_launch(void* const* d_in, const int* in_sizes, int n_in,
                              void* d_out, int out_size) {
    const float* wv = (const float*)d_in[0];
    const int* rep_ids = (const int*)d_in[1];
    const int* rep_mask = (const int*)d_in[2];
    const int* lengths = (const int*)d_in[3];
    const int* len_mask = (const int*)d_in[4];
    float* out = (float*)d_out;

    const int vec_elems = PB * 2 * PS * PD;
    const int write_mask = (out_size > vec_elems) ? 1 : 0;

    pooling_kernel<<<PB * PS / 2, THREADS>>>(wv, rep_ids, rep_mask, lengths,
                                             len_mask, out, write_mask);
}

// round 10
// speedup vs baseline: 1.2386x; 1.2386x over previous
#include <cuda_runtime.h>
#include <cstdint>

// Problem constants (from reference setup_inputs)
#define PB 16
#define PL 4096
#define PD 768
#define PS 128
#define D4 (PD / 4)          // 192 float4 per row
#define THREADS D4           // one float4 column per thread
#define NWARPS (THREADS / 32)

__device__ __forceinline__ void acc4(const float4 (&v)[4], float4& a,
                                     int& cx, int& cy, int& cz, int& cw) {
#pragma unroll
    for (int k = 0; k < 4; k++) {
        a.x += v[k].x; a.y += v[k].y; a.z += v[k].z; a.w += v[k].w;
        cx += (v[k].x != 0.f);
        cy += (v[k].y != 0.f);
        cz += (v[k].z != 0.f);
        cw += (v[k].w != 0.f);
    }
}

// Streaming loads: touch-once data, evict-first so the 201MB stream does not
// sweep L2 (keeps lengths/ids/gather rows resident for cross-CTA reuse).
__device__ __forceinline__ void ld4(float4 (&v)[4], const float4* __restrict__ p) {
    v[0] = __ldcs(p + 0 * D4);
    v[1] = __ldcs(p + 1 * D4);
    v[2] = __ldcs(p + 2 * D4);
    v[3] = __ldcs(p + 3 * D4);
}

// One CTA per (b, s) — the R8 geometry (best measured). Explicit 2-stage
// rotating register pipeline: next 4-token batch's loads issue before the
// previous batch is accumulated. Gather row loaded in the prologue.
__global__ __launch_bounds__(THREADS, 8) void pooling_kernel(
    const float* __restrict__ wv,            // [B, L, D]
    const int* __restrict__ rep_ids,         // [B, S]
    const int* __restrict__ rep_mask,        // [B, S] bool as int32
    const int* __restrict__ lengths,         // [B, S]
    const int* __restrict__ len_mask,        // [B, S] bool as int32
    float* __restrict__ out,                 // [B, 2S, D] (+ mask tail)
    int write_mask)
{
    const int bs = blockIdx.x;
    const int b = bs >> 7;
    const int s = bs & (PS - 1);
    const int tid = threadIdx.x;
    const int lane = tid & 31;
    const int wid = tid >> 5;

    __shared__ int sred[NWARPS];

    // ---- start = sum_{j < s} lengths[b, j] (block reduction) ----
    const int* lrow = lengths + b * PS;
    int part = (tid < s) ? __ldg(&lrow[tid]) : 0;    // tid<192 covers s<=127
#pragma unroll
    for (int o = 16; o > 0; o >>= 1)
        part += __shfl_down_sync(0xffffffffu, part, o);
    if (lane == 0) sred[wid] = part;
    __syncthreads();
    int start = 0;
#pragma unroll
    for (int w = 0; w < NWARPS; w++) start += sred[w];

    int len = __ldg(&lengths[bs]);
    int end = start + len;
    if (start > PL) start = PL;
    if (end > PL) end = PL;
    const int n = end - start;

    const float4* __restrict__ wvb =
        reinterpret_cast<const float4*>(wv) + (unsigned)b * (PL * D4);

    // ---- early gather load (independent of stream; overlaps latency) ----
    int id = __ldg(&rep_ids[bs]);
    if (id < 0) id = 0;
    if (id >= PL) id = PL - 1;
    float4 g = __ldg(&wvb[(unsigned)id * D4 + tid]);

    // ---- streamed segment sum + per-feature nonzero counts, pipelined ----
    const float4* __restrict__ p = wvb + (unsigned)start * D4 + tid;

    float4 acc = make_float4(0.f, 0.f, 0.f, 0.f);
    int cx = 0, cy = 0, cz = 0, cw = 0;

    float4 va[4], vb[4];
    const int nb = n >> 2;          // number of 4-token batches
    if (nb > 0) {
        ld4(va, p); p += 4 * D4;    // stage fill
        int i = 1;
        for (; i + 1 < nb; i += 2) {
            ld4(vb, p); p += 4 * D4;            // issue B
            acc4(va, acc, cx, cy, cz, cw);      // consume A
            ld4(va, p); p += 4 * D4;            // issue A'
            acc4(vb, acc, cx, cy, cz, cw);      // consume B
        }
        if (i < nb) {               // one remaining full batch
            ld4(vb, p); p += 4 * D4;
            acc4(va, acc, cx, cy, cz, cw);
            acc4(vb, acc, cx, cy, cz, cw);
        } else {
            acc4(va, acc, cx, cy, cz, cw);
        }
    }
    for (int r = n & 3; r > 0; r--) {           // tail tokens
        float4 v = __ldcs(p); p += D4;
        acc.x += v.x; acc.y += v.y; acc.z += v.z; acc.w += v.w;
        cx += (v.x != 0.f); cy += (v.y != 0.f);
        cz += (v.z != 0.f); cw += (v.w != 0.f);
    }

    // ---- block-reduce total nonzero count ----
    int nz = cx + cy + cz + cw;
#pragma unroll
    for (int o = 16; o > 0; o >>= 1)
        nz += __shfl_down_sync(0xffffffffu, nz, o);
    __syncthreads();                // sred reuse
    if (lane == 0) sred[wid] = nz;
    __syncthreads();
    int total_nz = 0;
#pragma unroll
    for (int w = 0; w < NWARPS; w++) total_nz += sred[w];

    const float mlen = len_mask[bs] ? 1.f : 0.f;
    const float mrep = rep_mask[bs] ? 1.f : 0.f;

    float4 mv;
    if (total_nz == 0) {
        mv = __ldg(&reinterpret_cast<const float4*>(wv)[tid]);  // wv[0,0,:]
    } else {
        mv.x = acc.x / (float)(cx ? cx : 1);
        mv.y = acc.y / (float)(cy ? cy : 1);
        mv.z = acc.z / (float)(cz ? cz : 1);
        mv.w = acc.w / (float)(cw ? cw : 1);
    }
    mv.x *= mlen; mv.y *= mlen; mv.z *= mlen; mv.w *= mlen;

    float4* __restrict__ outb =
        reinterpret_cast<float4*>(out) + (unsigned)b * (2 * PS * D4);
    __stcs(&outb[(unsigned)(PS + s) * D4 + tid], mv);           // mean row

    g.x *= mrep; g.y *= mrep; g.z *= mrep; g.w *= mrep;
    __stcs(&outb[(unsigned)s * D4 + tid], g);                   // rep row

    if (write_mask && tid == 0) {
        float* mo = out + (size_t)PB * 2 * PS * PD;
        mo[b * 2 * PS + s] = mrep;
        mo[b * 2 * PS + PS + s] = mlen;
    }
}

extern "C" void kernel_launch(void* const* d_in, const int* in_sizes, int n_in,
                              void* d_out, int out_size) {
    const float* wv = (const float*)d_in[0];
    const int* rep_ids = (const int*)d_in[1];
    const int* rep_mask = (const int*)d_in[2];
    const int* lengths = (const int*)d_in[3];
    const int* len_mask = (const int*)d_in[4];
    float* out = (float*)d_out;

    const int vec_elems = PB * 2 * PS * PD;
    const int write_mask = (out_size > vec_elems) ? 1 : 0;

    pooling_kernel<<<PB * PS, THREADS>>>(wv, rep_ids, rep_mask, lengths,
                                         len_mask, out, write_mask);
}